// round 14
// baseline (speedup 1.0000x reference)
#include <cuda_runtime.h>
#include <cuda_bf16.h>
#include <cstdint>

// GradPooling: out[b,oh,ow,c] = sel ? max2x2 : mean2x2
//   sel = 2*(|x[oh+1,ow+1]-x[oh,ow+1]| + |x[oh+1,ow+1]-x[oh+1,ow]|) > lamb
//   pool window = x rows {2oh-1,2oh} x cols {2ow-1,2ow}, OOB -> 0.0
// x (32,224,224,64) f32 NHWC, out (32,112,112,64) f32.
//
// R11: R4 body (ow-pair per thread) + 4-iter loop where the 8 pool loads are
//      cp.async.cg into double-buffered smem (issued for iter i+1 BEFORE the
//      compute of iter i -> no inter-iteration LSU bubble, zero register cost
//      while in flight). Gradient taps stay as direct LDG. 144B per-thread
//      slot stride -> conflict-free LDS.128 / async-STS bank pattern.

#define B_    32
#define H_    224
#define W_    224
#define C_    64
#define OH_   112
#define OW_   112
#define OJ_   56          // ow-pairs
#define C4_   16          // float4 groups per pixel
#define ITER_ 4
#define NT_   ((B_ * OH_ * OJ_ * C4_) / ITER_)   // 802,816 threads

#define SLOT_       9                  // float4 per thread-buffer (8 used + 1 pad)
#define BUF_F4_     (256 * SLOT_)      // float4 per buffer
#define SMEM_BYTES_ (2 * BUF_F4_ * 16) // 73,728 B -> 3 CTAs/SM

__device__ __forceinline__ void cp16(uint32_t dst, const float4* src) {
    asm volatile("cp.async.cg.shared.global [%0], [%1], 16;" :: "r"(dst), "l"(src));
}

__global__ __launch_bounds__(256)
void gradpool_kernel(const float* __restrict__ x,
                     const float* __restrict__ lamb,
                     float* __restrict__ out)
{
    extern __shared__ float4 smem[];
    const int tx   = threadIdx.x;
    const int tid0 = blockIdx.x * 256 + tx;
    const float lam = __ldg(lamb);
    float4* const o4 = (float4*)out;
    const float4 z = make_float4(0.f, 0.f, 0.f, 0.f);

    float4* const my0 = smem + tx * SLOT_;
    float4* const my1 = smem + BUF_F4_ + tx * SLOT_;
    const uint32_t s0 = (uint32_t)__cvta_generic_to_shared(my0);
    const uint32_t s1 = (uint32_t)__cvta_generic_to_shared(my1);

    // Issue the 8 pool-window cp.asyncs (or STS zeros for OOB) for iteration `it`.
    auto issue = [&](int it) {
        const int tid = tid0 + it * NT_;
        const int c4 = tid & (C4_ - 1);
        int t = tid >> 4;
        const int j  = t % OJ_;  t /= OJ_;
        const int oh = t % OH_;
        const int bb = t / OH_;
        const float4* xb = (const float4*)(x) + (bb * H_ * W_) * C4_ + c4;
        const int h1 = 2 * oh;
        const int w0 = 4 * j - 1;
        float4*  my = (it & 1) ? my1 : my0;
        uint32_t sb = (it & 1) ? s1 : s0;

        const float4* r1 = xb + (h1 * W_ + w0) * C4_;      // pool row h1
        cp16(sb + 16, r1 + 1 * C4_);
        cp16(sb + 32, r1 + 2 * C4_);
        cp16(sb + 48, r1 + 3 * C4_);
        if (j > 0) cp16(sb, r1); else my[0] = z;
        if (oh > 0) {
            const float4* r0 = r1 - W_ * C4_;              // pool row h0 = h1-1
            cp16(sb + 80,  r0 + 1 * C4_);
            cp16(sb + 96,  r0 + 2 * C4_);
            cp16(sb + 112, r0 + 3 * C4_);
            if (j > 0) cp16(sb + 64, r0); else my[4] = z;
        } else {
            my[4] = z; my[5] = z; my[6] = z; my[7] = z;
        }
    };

    issue(0);
    asm volatile("cp.async.commit_group;" ::: "memory");

    #pragma unroll 1
    for (int it = 0; it < ITER_; it++) {
        // Prefetch next iteration's pool window BEFORE any compute of this one.
        if (it + 1 < ITER_) {
            issue(it + 1);
            asm volatile("cp.async.commit_group;" ::: "memory");
        }

        // Recompute this iteration's indices + gradient taps (direct LDG).
        const int tid = tid0 + it * NT_;
        const int c4 = tid & (C4_ - 1);
        int t = tid >> 4;
        const int j  = t % OJ_;  t /= OJ_;
        const int oh = t % OH_;
        const int bb = t / OH_;
        const float4* xb = (const float4*)(x) + (bb * H_ * W_) * C4_ + c4;
        const int gw = 2 * j;
        const float4* gu = xb + (oh * W_ + gw) * C4_;        // row oh
        const float4* gc = gu + W_ * C4_;                    // row oh+1
        float4 upL  = gu[1 * C4_];
        float4 upR  = gu[2 * C4_];
        float4 lfL  = gc[0];
        float4 ctrL = gc[1 * C4_];
        float4 ctrR = gc[2 * C4_];    // right pixel's left tap == ctrL

        // Wait for THIS iteration's pool data (leave the just-issued group in flight).
        if (it + 1 < ITER_) asm volatile("cp.async.wait_group 1;" ::: "memory");
        else                asm volatile("cp.async.wait_group 0;" ::: "memory");

        const float4* my = (it & 1) ? my1 : my0;
        float4 b00 = my[0], b01 = my[1], b02 = my[2], b03 = my[3];
        float4 a00 = my[4], a01 = my[5], a02 = my[6], a03 = my[7];

        float4 oL, oR;
#define COMP(f)                                                                \
        {                                                                      \
            float mxL = fmaxf(fmaxf(a00.f, a01.f), fmaxf(b00.f, b01.f));       \
            float mnL = (a00.f + a01.f + b00.f + b01.f) * 0.25f;               \
            float dL = 2.0f * (fabsf(ctrL.f - upL.f) + fabsf(ctrL.f - lfL.f)); \
            oL.f = (dL > lam) ? mxL : mnL;                                     \
        }
        COMP(x) COMP(y) COMP(z) COMP(w)
#undef COMP
#define COMPR(f)                                                               \
        {                                                                      \
            float mxR = fmaxf(fmaxf(a02.f, a03.f), fmaxf(b02.f, b03.f));       \
            float mnR = (a02.f + a03.f + b02.f + b03.f) * 0.25f;               \
            float dR = 2.0f * (fabsf(ctrR.f - upR.f) + fabsf(ctrR.f - ctrL.f));\
            oR.f = (dR > lam) ? mxR : mnR;                                     \
        }
        COMPR(x) COMPR(y) COMPR(z) COMPR(w)
#undef COMPR

        const int pL = (bb * OH_ + oh) * OW_ + 2 * j;
        o4[pL * C4_ + c4]       = oL;
        o4[(pL + 1) * C4_ + c4] = oR;
    }
}

extern "C" void kernel_launch(void* const* d_in, const int* in_sizes, int n_in,
                              void* d_out, int out_size)
{
    const float* x    = (const float*)d_in[0];
    const float* lamb = (const float*)d_in[1];
    if (n_in >= 2 && in_sizes[0] == 1) {             // guard against metadata order
        x    = (const float*)d_in[1];
        lamb = (const float*)d_in[0];
    }

    cudaFuncSetAttribute(gradpool_kernel,
                         cudaFuncAttributeMaxDynamicSharedMemorySize, SMEM_BYTES_);

    const int threads = 256;
    const int blocks = NT_ / threads;                // 3136, exact
    gradpool_kernel<<<blocks, threads, SMEM_BYTES_>>>(x, lamb, (float*)d_out);
}

// round 15
// speedup vs baseline: 1.4902x; 1.4902x over previous
#include <cuda_runtime.h>
#include <cuda_bf16.h>

// GradPooling: out[b,oh,ow,c] = sel ? max2x2 : mean2x2
//   sel = 2*(|x[oh+1,ow+1]-x[oh,ow+1]| + |x[oh+1,ow+1]-x[oh+1,ow]|) > lamb
//   pool window = x rows {2oh-1,2oh} x cols {2ow-1,2ow}, OOB -> 0.0
//   (zero participates in max; mean divisor fixed at 4)
// x (32,224,224,64) f32 NHWC, out (32,112,112,64) f32.
//
// R14: exact R4 structure (proven optimum: ow-pair per thread, 13 front-batched
//      float4 LDGs, 64 regs, 4 CTAs/SM) + __stcs evict-first streaming stores
//      for the write-once output. All other variants (R5 spill, R6 quad,
//      R9 loop, R11 cp.async) regressed; see commit log.

#define B_   32
#define H_   224
#define W_   224
#define C_   64
#define OH_  112
#define OW_  112
#define OJ_  (OW_ / 2)   // 56 ow-pairs
#define C4_  (C_ / 4)    // 16 float4 groups per pixel

__global__ __launch_bounds__(256)
void gradpool_kernel(const float* __restrict__ x,
                     const float* __restrict__ lamb,
                     float* __restrict__ out)
{
    const int tid = blockIdx.x * blockDim.x + threadIdx.x;

    const int c4 = tid & (C4_ - 1);
    int t = tid >> 4;
    const int j  = t % OJ_;  t /= OJ_;
    const int oh = t % OH_;
    const int b  = t / OH_;

    const float lam = __ldg(lamb);

    const float4* xb = (const float4*)(x) + ((b * H_) * W_) * C4_ + c4;
    #define XV(h, w) xb[((h) * W_ + (w)) * C4_]

    // ---- pool windows: rows {2oh-1, 2oh}, cols {4j-1..4j+2} ----
    const int h0 = 2 * oh - 1;
    const int h1 = 2 * oh;
    const int w0 = 4 * j - 1;

    const float4 z = make_float4(0.f, 0.f, 0.f, 0.f);
    float4 a00 = z, a01, a02, a03;          // row h0
    float4 b00 = z, b01, b02, b03;          // row h1
    b01 = XV(h1, w0 + 1);
    b02 = XV(h1, w0 + 2);
    b03 = XV(h1, w0 + 3);
    if (j > 0) b00 = XV(h1, w0);
    if (oh > 0) {
        a01 = XV(h0, w0 + 1);
        a02 = XV(h0, w0 + 2);
        a03 = XV(h0, w0 + 3);
        if (j > 0) a00 = XV(h0, w0);
    } else {
        a01 = z; a02 = z; a03 = z;
    }

    // ---- gradient taps (rows oh..oh+1 <= 112, cols 2j..2j+2 <= 112) ----
    const int gw = 2 * j;
    float4 upL  = XV(oh,     gw + 1);
    float4 upR  = XV(oh,     gw + 2);
    float4 lfL  = XV(oh + 1, gw);
    float4 ctrL = XV(oh + 1, gw + 1);
    float4 ctrR = XV(oh + 1, gw + 2);   // right pixel's left tap == ctrL
    #undef XV

    float4 oL, oR;
#define COMP(f)                                                                \
    {                                                                          \
        float mxL = fmaxf(fmaxf(a00.f, a01.f), fmaxf(b00.f, b01.f));           \
        float mnL = (a00.f + a01.f + b00.f + b01.f) * 0.25f;                   \
        float dL = 2.0f * (fabsf(ctrL.f - upL.f) + fabsf(ctrL.f - lfL.f));     \
        oL.f = (dL > lam) ? mxL : mnL;                                         \
    }
    COMP(x) COMP(y) COMP(z) COMP(w)
#undef COMP
#define COMPR(f)                                                               \
    {                                                                          \
        float mxR = fmaxf(fmaxf(a02.f, a03.f), fmaxf(b02.f, b03.f));           \
        float mnR = (a02.f + a03.f + b02.f + b03.f) * 0.25f;                   \
        float dR = 2.0f * (fabsf(ctrR.f - upR.f) + fabsf(ctrR.f - ctrL.f));    \
        oR.f = (dR > lam) ? mxR : mnR;                                         \
    }
    COMPR(x) COMPR(y) COMPR(z) COMPR(w)
#undef COMPR

    const int pL = (b * OH_ + oh) * OW_ + 2 * j;     // left output pixel
    float4* o4 = (float4*)out;
    __stcs(&o4[pL * C4_ + c4],       oL);            // evict-first streaming store
    __stcs(&o4[(pL + 1) * C4_ + c4], oR);
}

extern "C" void kernel_launch(void* const* d_in, const int* in_sizes, int n_in,
                              void* d_out, int out_size)
{
    const float* x    = (const float*)d_in[0];
    const float* lamb = (const float*)d_in[1];
    if (n_in >= 2 && in_sizes[0] == 1) {             // guard against metadata order
        x    = (const float*)d_in[1];
        lamb = (const float*)d_in[0];
    }

    const int total = B_ * OH_ * OJ_ * C4_;          // 3,211,264 threads
    const int threads = 256;
    const int blocks = total / threads;              // 12544, exact
    gradpool_kernel<<<blocks, threads>>>(x, lamb, (float*)d_out);
}